// round 15
// baseline (speedup 1.0000x reference)
#include <cuda_runtime.h>
#include <cstdint>

// MagNorm EMA normalize. x [32, 4096, 481] f32, mu0 [32, 481] f32.
//
// Calibrated models (R12-R14): bench time = bytes / sustained-BW, with
// sustained BW 6.03 TB/s @128 CTAs, 5.90 @96 CTAs (~2% penalty per step
// down in concurrency) — while each warm span costs ~25 MB (~4%).
// R15: NSPLIT 3 -> 2. Traffic 546.6 -> 528.9 MB (W back to 416 steps for
// error margin; one boundary only -> rel_err ~2-3e-4). Feasibility at 64
// CTAs: per-tile budget ~1210 cyc vs ~1000 cyc compute -> still memory-
// paced; LOOK=5 (154 kB/CTA reads in flight) unchanged. Spans cost-
// balanced: emits 135/121 + 26 warm -> R+W 270/268 tiles per CTA.
// Engine identical to R11-R14: TT=16, NBUF=7, LOOK=5, hoisted reload,
// in-place write-back, wait_group.read ring safety.

#define MN_F 481
#define MN_T 4096
#define MN_B 32
#define TT   16
#define TILE_ELEMS (TT * MN_F)            // 7696
#define TILE_BYTES (TILE_ELEMS * 4)       // 30784 (16B multiple)
#define NBUF  7
#define LOOK  5                           // load lookahead in tiles
#define W_TILES 26                        // 416 warmup steps
#define NSPLIT 2

#define SMEM_DATA  64
#define SMEM_TOTAL (64 + NBUF * TILE_BYTES)   // 215,552 B

__device__ __forceinline__ uint32_t smem_addr_u32(const void* p) {
    uint32_t a;
    asm("{ .reg .u64 t; cvta.to.shared.u64 t, %1; cvt.u32.u64 %0, t; }"
        : "=r"(a) : "l"(p));
    return a;
}
__device__ __forceinline__ void mbar_init(uint32_t bar, uint32_t cnt) {
    asm volatile("mbarrier.init.shared.b64 [%0], %1;" :: "r"(bar), "r"(cnt) : "memory");
}
__device__ __forceinline__ void mbar_expect(uint32_t bar, uint32_t bytes) {
    asm volatile("mbarrier.arrive.expect_tx.shared.b64 _, [%0], %1;"
                 :: "r"(bar), "r"(bytes) : "memory");
}
__device__ __forceinline__ void mbar_wait(uint32_t bar, uint32_t parity) {
    asm volatile(
        "{\n\t"
        ".reg .pred P;\n\t"
        "WAIT_%=:\n\t"
        "mbarrier.try_wait.parity.acquire.cta.shared::cta.b64 P, [%0], %1, 0x989680;\n\t"
        "@P bra DONE_%=;\n\t"
        "bra WAIT_%=;\n\t"
        "DONE_%=:\n\t"
        "}" :: "r"(bar), "r"(parity) : "memory");
}
__device__ __forceinline__ void bulk_g2s(uint32_t dst, const void* src,
                                         uint32_t bytes, uint32_t bar) {
    asm volatile(
        "cp.async.bulk.shared::cluster.global.mbarrier::complete_tx::bytes "
        "[%0], [%1], %2, [%3];"
        :: "r"(dst), "l"(src), "r"(bytes), "r"(bar) : "memory");
}
__device__ __forceinline__ void bulk_s2g_commit(void* dst, uint32_t src, uint32_t bytes) {
    asm volatile("cp.async.bulk.global.shared::cta.bulk_group [%0], [%1], %2;"
                 :: "l"(dst), "r"(src), "r"(bytes) : "memory");
    asm volatile("cp.async.bulk.commit_group;" ::: "memory");
}
__device__ __forceinline__ void bulk_store_wait_read1() {
    asm volatile("cp.async.bulk.wait_group.read 1;" ::: "memory");
}
__device__ __forceinline__ void bulk_store_wait0() {
    asm volatile("cp.async.bulk.wait_group 0;" ::: "memory");
}
__device__ __forceinline__ void fence_proxy_async_s() {
    asm volatile("fence.proxy.async.shared::cta;" ::: "memory");
}

__global__ void __launch_bounds__(512, 1)
magnorm_kernel(const float* __restrict__ x,
               const float* __restrict__ mu0,
               float* __restrict__ out)
{
    extern __shared__ char smem[];
    const uint32_t sbase = smem_addr_u32(smem);

    const int tid = threadIdx.x;
    const int b   = blockIdx.x / NSPLIT;
    const int s   = blockIdx.x - b * NSPLIT;
    const int f   = tid;                  // channel; threads 481..511 idle in compute

    // Cost-balanced emit spans (256 emit tiles per batch):
    // s0 [0,135) no warm; s1 [135,256) warm 26 tiles.
    // Per-CTA byte-cost (R tiles + W tiles): 270 / 268.
    const int emit_start = (s == 0) ? 0   : 135;
    const int emit_end   = (s == 0) ? 135 : 256;
    const int warm       = (s == 0) ? 0 : W_TILES;
    const int t_first    = emit_start - warm;
    const int ntiles     = emit_end - t_first;

    const size_t base = (size_t)b * MN_T * MN_F;
    const float* px   = x   + base;
    float*       pout = out + base;

    float mu, var;
    if (s == 0) { mu = (f < MN_F) ? __ldg(mu0 + b * MN_F + f) : 0.0f; var = 1600.0f; }
    else        { mu = 0.0f; var = 1.0f; }

    if (tid == 0) {
#pragma unroll
        for (int k = 0; k < NBUF; k++) mbar_init(sbase + 8 * k, 1);
    }
    __syncthreads();

    // Prologue: kick off LOOK tile loads into bufs 0..LOOK-1.
    if (tid == 0) {
#pragma unroll
        for (int k = 0; k < LOOK; k++) {
            const uint32_t bar = sbase + 8 * k;
            mbar_expect(bar, TILE_BYTES);
            bulk_g2s(sbase + SMEM_DATA + k * TILE_BYTES,
                     px + (size_t)(t_first + k) * TILE_ELEMS, TILE_BYTES, bar);
        }
    }

    int buf = 0, phase = 0;               // buf = i % NBUF, phase = (i/NBUF)&1
    for (int i = 0; i < ntiles; i++) {
        const uint32_t bar   = sbase + 8 * buf;
        const uint32_t bufsa = sbase + SMEM_DATA + buf * TILE_BYTES;
        mbar_wait(bar, phase);

        // Hoisted reload: issue the i+LOOK load NOW so it overlaps compute.
        // Buffer (i+LOOK)%NBUF was consumed at tile i-2 (all threads are past
        // barrier(i-1)); wait_group.read 1 leaves only store(i-1) pending, so
        // store(i-2)'s SMEM reads have drained (FIFO bulk group).
        if (tid == 0) {
            const int j = i + LOOK;
            if (j < ntiles) {
                bulk_store_wait_read1();
                int jb = buf + LOOK; if (jb >= NBUF) jb -= NBUF;
                const uint32_t jbar = sbase + 8 * jb;
                mbar_expect(jbar, TILE_BYTES);
                bulk_g2s(sbase + SMEM_DATA + jb * TILE_BYTES,
                         px + (size_t)(t_first + j) * TILE_ELEMS, TILE_BYTES, jbar);
            }
        }

        const bool emit = (i >= warm);    // uniform across CTA
        if (f < MN_F) {
            float* row = (float*)(smem + SMEM_DATA + buf * TILE_BYTES) + f;
            if (emit) {
#pragma unroll
                for (int t = 0; t < TT; t++) {
                    const float xv = row[t * MN_F];
                    const float e  = xv - mu;         // x_t - mu_{t-1}
                    mu = fmaf(0.01f, e, mu);
                    const float d  = 0.99f * e;       // x_t - mu_t
                    var = fmaf(0.99f, var, 0.01f * (d * d));
                    row[t * MN_F] = d * rsqrtf(var);  // in-place write-back
                }
            } else {
#pragma unroll
                for (int t = 0; t < TT; t++) {
                    const float xv = row[t * MN_F];
                    const float e  = xv - mu;
                    mu = fmaf(0.01f, e, mu);
                    const float d  = 0.99f * e;
                    var = fmaf(0.99f, var, 0.01f * (d * d));
                }
            }
        }

        // All columns written (skew bounded to <1 tile) before the S2G and
        // before the next tile's hoisted reload can touch older buffers.
        __syncthreads();

        if (tid == 0 && emit) {
            fence_proxy_async_s();
            bulk_s2g_commit(pout + (size_t)(t_first + i) * TILE_ELEMS,
                            bufsa, TILE_BYTES);
        }

        if (++buf == NBUF) { buf = 0; phase ^= 1; }
    }
    if (tid == 0) bulk_store_wait0();
}

extern "C" void kernel_launch(void* const* d_in, const int* in_sizes, int n_in,
                              void* d_out, int out_size)
{
    const float* x   = (const float*)d_in[0];
    const float* mu0 = (const float*)d_in[1];
    if (n_in >= 2 && in_sizes[0] < in_sizes[1]) {
        x   = (const float*)d_in[1];
        mu0 = (const float*)d_in[0];
    }
    float* out = (float*)d_out;

    cudaFuncSetAttribute(magnorm_kernel,
                         cudaFuncAttributeMaxDynamicSharedMemorySize, SMEM_TOTAL);
    magnorm_kernel<<<MN_B * NSPLIT, 512, SMEM_TOTAL>>>(x, mu0, out);
}

// round 16
// speedup vs baseline: 1.0891x; 1.0891x over previous
#include <cuda_runtime.h>
#include <cstdint>

// MagNorm EMA normalize. x [32, 4096, 481] f32, mu0 [32, 481] f32.
//
// R15 post-mortem: 64 CTAs collapse to 4.73 TB/s (CTA-pace limited) ->
// NSPLIT=3 / 96 CTAs is the measured optimum (ladder: 128->6.03, 96->5.90,
// 64->4.73 TB/s; the 4th warm span costs more than 128-CTA BW recovers).
// R16 = R14 engine reverted + last calibrated warmup trim: W 352 -> 320
// steps. Error ladder (x1.35-1.38 per 32 steps, 3 measured points) predicts
// rel_err ~6.0e-4 (1.67x margin). Traffic 546.6 -> 542.7 MB. Spans
// rebalanced: emits 92/82/82, warm 20 -> per-CTA R+W cost 184/184/184.
// Engine: TT=16, NBUF=7, LOOK=5, hoisted reload, in-place write-back,
// wait_group.read ring safety (unchanged since R11).

#define MN_F 481
#define MN_T 4096
#define MN_B 32
#define TT   16
#define TILE_ELEMS (TT * MN_F)            // 7696
#define TILE_BYTES (TILE_ELEMS * 4)       // 30784 (16B multiple)
#define NBUF  7
#define LOOK  5                           // load lookahead in tiles
#define W_TILES 20                        // 320 warmup steps
#define NSPLIT 3

#define SMEM_DATA  64
#define SMEM_TOTAL (64 + NBUF * TILE_BYTES)   // 215,552 B

__device__ __forceinline__ uint32_t smem_addr_u32(const void* p) {
    uint32_t a;
    asm("{ .reg .u64 t; cvta.to.shared.u64 t, %1; cvt.u32.u64 %0, t; }"
        : "=r"(a) : "l"(p));
    return a;
}
__device__ __forceinline__ void mbar_init(uint32_t bar, uint32_t cnt) {
    asm volatile("mbarrier.init.shared.b64 [%0], %1;" :: "r"(bar), "r"(cnt) : "memory");
}
__device__ __forceinline__ void mbar_expect(uint32_t bar, uint32_t bytes) {
    asm volatile("mbarrier.arrive.expect_tx.shared.b64 _, [%0], %1;"
                 :: "r"(bar), "r"(bytes) : "memory");
}
__device__ __forceinline__ void mbar_wait(uint32_t bar, uint32_t parity) {
    asm volatile(
        "{\n\t"
        ".reg .pred P;\n\t"
        "WAIT_%=:\n\t"
        "mbarrier.try_wait.parity.acquire.cta.shared::cta.b64 P, [%0], %1, 0x989680;\n\t"
        "@P bra DONE_%=;\n\t"
        "bra WAIT_%=;\n\t"
        "DONE_%=:\n\t"
        "}" :: "r"(bar), "r"(parity) : "memory");
}
__device__ __forceinline__ void bulk_g2s(uint32_t dst, const void* src,
                                         uint32_t bytes, uint32_t bar) {
    asm volatile(
        "cp.async.bulk.shared::cluster.global.mbarrier::complete_tx::bytes "
        "[%0], [%1], %2, [%3];"
        :: "r"(dst), "l"(src), "r"(bytes), "r"(bar) : "memory");
}
__device__ __forceinline__ void bulk_s2g_commit(void* dst, uint32_t src, uint32_t bytes) {
    asm volatile("cp.async.bulk.global.shared::cta.bulk_group [%0], [%1], %2;"
                 :: "l"(dst), "r"(src), "r"(bytes) : "memory");
    asm volatile("cp.async.bulk.commit_group;" ::: "memory");
}
__device__ __forceinline__ void bulk_store_wait_read1() {
    asm volatile("cp.async.bulk.wait_group.read 1;" ::: "memory");
}
__device__ __forceinline__ void bulk_store_wait0() {
    asm volatile("cp.async.bulk.wait_group 0;" ::: "memory");
}
__device__ __forceinline__ void fence_proxy_async_s() {
    asm volatile("fence.proxy.async.shared::cta;" ::: "memory");
}

__global__ void __launch_bounds__(512, 1)
magnorm_kernel(const float* __restrict__ x,
               const float* __restrict__ mu0,
               float* __restrict__ out)
{
    extern __shared__ char smem[];
    const uint32_t sbase = smem_addr_u32(smem);

    const int tid = threadIdx.x;
    const int b   = blockIdx.x / NSPLIT;
    const int s   = blockIdx.x - b * NSPLIT;
    const int f   = tid;                  // channel; threads 481..511 idle in compute

    // Cost-balanced emit spans (256 emit tiles per batch):
    // s0 [0,92) no warm; s1 [92,174) warm 20; s2 [174,256) warm 20.
    // Per-CTA byte-cost (R tiles + W tiles): 184 / 184 / 184.
    const int emit_start = (s == 0) ? 0  : (s == 1) ? 92  : 174;
    const int emit_end   = (s == 0) ? 92 : (s == 1) ? 174 : 256;
    const int warm       = (s == 0) ? 0 : W_TILES;
    const int t_first    = emit_start - warm;
    const int ntiles     = emit_end - t_first;

    const size_t base = (size_t)b * MN_T * MN_F;
    const float* px   = x   + base;
    float*       pout = out + base;

    float mu, var;
    if (s == 0) { mu = (f < MN_F) ? __ldg(mu0 + b * MN_F + f) : 0.0f; var = 1600.0f; }
    else        { mu = 0.0f; var = 1.0f; }

    if (tid == 0) {
#pragma unroll
        for (int k = 0; k < NBUF; k++) mbar_init(sbase + 8 * k, 1);
    }
    __syncthreads();

    // Prologue: kick off LOOK tile loads into bufs 0..LOOK-1.
    if (tid == 0) {
#pragma unroll
        for (int k = 0; k < LOOK; k++) {
            const uint32_t bar = sbase + 8 * k;
            mbar_expect(bar, TILE_BYTES);
            bulk_g2s(sbase + SMEM_DATA + k * TILE_BYTES,
                     px + (size_t)(t_first + k) * TILE_ELEMS, TILE_BYTES, bar);
        }
    }

    int buf = 0, phase = 0;               // buf = i % NBUF, phase = (i/NBUF)&1
    for (int i = 0; i < ntiles; i++) {
        const uint32_t bar   = sbase + 8 * buf;
        const uint32_t bufsa = sbase + SMEM_DATA + buf * TILE_BYTES;
        mbar_wait(bar, phase);

        // Hoisted reload: issue the i+LOOK load NOW so it overlaps compute.
        // Buffer (i+LOOK)%NBUF was consumed at tile i-2 (all threads are past
        // barrier(i-1)); wait_group.read 1 leaves only store(i-1) pending, so
        // store(i-2)'s SMEM reads have drained (FIFO bulk group).
        if (tid == 0) {
            const int j = i + LOOK;
            if (j < ntiles) {
                bulk_store_wait_read1();
                int jb = buf + LOOK; if (jb >= NBUF) jb -= NBUF;
                const uint32_t jbar = sbase + 8 * jb;
                mbar_expect(jbar, TILE_BYTES);
                bulk_g2s(sbase + SMEM_DATA + jb * TILE_BYTES,
                         px + (size_t)(t_first + j) * TILE_ELEMS, TILE_BYTES, jbar);
            }
        }

        const bool emit = (i >= warm);    // uniform across CTA
        if (f < MN_F) {
            float* row = (float*)(smem + SMEM_DATA + buf * TILE_BYTES) + f;
            if (emit) {
#pragma unroll
                for (int t = 0; t < TT; t++) {
                    const float xv = row[t * MN_F];
                    const float e  = xv - mu;         // x_t - mu_{t-1}
                    mu = fmaf(0.01f, e, mu);
                    const float d  = 0.99f * e;       // x_t - mu_t
                    var = fmaf(0.99f, var, 0.01f * (d * d));
                    row[t * MN_F] = d * rsqrtf(var);  // in-place write-back
                }
            } else {
#pragma unroll
                for (int t = 0; t < TT; t++) {
                    const float xv = row[t * MN_F];
                    const float e  = xv - mu;
                    mu = fmaf(0.01f, e, mu);
                    const float d  = 0.99f * e;
                    var = fmaf(0.99f, var, 0.01f * (d * d));
                }
            }
        }

        // All columns written (skew bounded to <1 tile) before the S2G and
        // before the next tile's hoisted reload can touch older buffers.
        __syncthreads();

        if (tid == 0 && emit) {
            fence_proxy_async_s();
            bulk_s2g_commit(pout + (size_t)(t_first + i) * TILE_ELEMS,
                            bufsa, TILE_BYTES);
        }

        if (++buf == NBUF) { buf = 0; phase ^= 1; }
    }
    if (tid == 0) bulk_store_wait0();
}

extern "C" void kernel_launch(void* const* d_in, const int* in_sizes, int n_in,
                              void* d_out, int out_size)
{
    const float* x   = (const float*)d_in[0];
    const float* mu0 = (const float*)d_in[1];
    if (n_in >= 2 && in_sizes[0] < in_sizes[1]) {
        x   = (const float*)d_in[1];
        mu0 = (const float*)d_in[0];
    }
    float* out = (float*)d_out;

    cudaFuncSetAttribute(magnorm_kernel,
                         cudaFuncAttributeMaxDynamicSharedMemorySize, SMEM_TOTAL);
    magnorm_kernel<<<MN_B * NSPLIT, 512, SMEM_TOTAL>>>(x, mu0, out);
}

// round 17
// speedup vs baseline: 1.1848x; 1.0879x over previous
#include <cuda_runtime.h>
#include <cstdint>

// MagNorm EMA normalize. x [32, 4096, 481] f32, mu0 [32, 481] f32.
//
// FINAL (= R14, the measured optimum; R16's W=320 trim regressed within
// BW noise while burning error margin -> reverted per pre-registered rule).
//
// Design summary (16 rounds of evidence):
// - Scalar-LDG register pipelines plateau at 4.0 TB/s regardless of MLP
//   depth, warp count, prefetch, or alignment -> request-stream-shape cap.
// - cp.async.bulk SMEM staging breaks it: tile = 16 timesteps x 481 chans
//   = one contiguous 30,784B span; 7-buffer ring, loads hoisted to overlap
//   compute 5 tiles ahead; in-place write-back (thread f owns column f);
//   S2G bulk stores; wait_group.read ring safety.
// - 3-way T-split with 352-step EMA warmup (0.99^352 residual); calibrated
//   rel_err 4.38e-4 (2.3x under the 1e-3 gate). 96 CTAs = measured optimum
//   on the concurrency/traffic ladder (128->6.03, 96->5.90, 64->4.73 TB/s).
// - Spans cost-balanced: emits 93/82/81 + 22 warm -> R+W 186/186/184.
// Traffic 546.6 MB at ~5.9 TB/s sustained -> ~92.7us (2.23x vs R1's 206.6).

#define MN_F 481
#define MN_T 4096
#define MN_B 32
#define TT   16
#define TILE_ELEMS (TT * MN_F)            // 7696
#define TILE_BYTES (TILE_ELEMS * 4)       // 30784 (16B multiple)
#define NBUF  7
#define LOOK  5                           // load lookahead in tiles
#define W_TILES 22                        // 352 warmup steps
#define NSPLIT 3

#define SMEM_DATA  64
#define SMEM_TOTAL (64 + NBUF * TILE_BYTES)   // 215,552 B

__device__ __forceinline__ uint32_t smem_addr_u32(const void* p) {
    uint32_t a;
    asm("{ .reg .u64 t; cvta.to.shared.u64 t, %1; cvt.u32.u64 %0, t; }"
        : "=r"(a) : "l"(p));
    return a;
}
__device__ __forceinline__ void mbar_init(uint32_t bar, uint32_t cnt) {
    asm volatile("mbarrier.init.shared.b64 [%0], %1;" :: "r"(bar), "r"(cnt) : "memory");
}
__device__ __forceinline__ void mbar_expect(uint32_t bar, uint32_t bytes) {
    asm volatile("mbarrier.arrive.expect_tx.shared.b64 _, [%0], %1;"
                 :: "r"(bar), "r"(bytes) : "memory");
}
__device__ __forceinline__ void mbar_wait(uint32_t bar, uint32_t parity) {
    asm volatile(
        "{\n\t"
        ".reg .pred P;\n\t"
        "WAIT_%=:\n\t"
        "mbarrier.try_wait.parity.acquire.cta.shared::cta.b64 P, [%0], %1, 0x989680;\n\t"
        "@P bra DONE_%=;\n\t"
        "bra WAIT_%=;\n\t"
        "DONE_%=:\n\t"
        "}" :: "r"(bar), "r"(parity) : "memory");
}
__device__ __forceinline__ void bulk_g2s(uint32_t dst, const void* src,
                                         uint32_t bytes, uint32_t bar) {
    asm volatile(
        "cp.async.bulk.shared::cluster.global.mbarrier::complete_tx::bytes "
        "[%0], [%1], %2, [%3];"
        :: "r"(dst), "l"(src), "r"(bytes), "r"(bar) : "memory");
}
__device__ __forceinline__ void bulk_s2g_commit(void* dst, uint32_t src, uint32_t bytes) {
    asm volatile("cp.async.bulk.global.shared::cta.bulk_group [%0], [%1], %2;"
                 :: "l"(dst), "r"(src), "r"(bytes) : "memory");
    asm volatile("cp.async.bulk.commit_group;" ::: "memory");
}
__device__ __forceinline__ void bulk_store_wait_read1() {
    asm volatile("cp.async.bulk.wait_group.read 1;" ::: "memory");
}
__device__ __forceinline__ void bulk_store_wait0() {
    asm volatile("cp.async.bulk.wait_group 0;" ::: "memory");
}
__device__ __forceinline__ void fence_proxy_async_s() {
    asm volatile("fence.proxy.async.shared::cta;" ::: "memory");
}

__global__ void __launch_bounds__(512, 1)
magnorm_kernel(const float* __restrict__ x,
               const float* __restrict__ mu0,
               float* __restrict__ out)
{
    extern __shared__ char smem[];
    const uint32_t sbase = smem_addr_u32(smem);

    const int tid = threadIdx.x;
    const int b   = blockIdx.x / NSPLIT;
    const int s   = blockIdx.x - b * NSPLIT;
    const int f   = tid;                  // channel; threads 481..511 idle in compute

    // Cost-balanced emit spans (256 emit tiles per batch):
    // s0 [0,93) no warm; s1 [93,175) warm 22; s2 [175,256) warm 22.
    // Per-CTA byte-cost (R tiles + W tiles): 186 / 186 / 184.
    const int emit_start = (s == 0) ? 0  : (s == 1) ? 93  : 175;
    const int emit_end   = (s == 0) ? 93 : (s == 1) ? 175 : 256;
    const int warm       = (s == 0) ? 0 : W_TILES;
    const int t_first    = emit_start - warm;
    const int ntiles     = emit_end - t_first;

    const size_t base = (size_t)b * MN_T * MN_F;
    const float* px   = x   + base;
    float*       pout = out + base;

    float mu, var;
    if (s == 0) { mu = (f < MN_F) ? __ldg(mu0 + b * MN_F + f) : 0.0f; var = 1600.0f; }
    else        { mu = 0.0f; var = 1.0f; }

    if (tid == 0) {
#pragma unroll
        for (int k = 0; k < NBUF; k++) mbar_init(sbase + 8 * k, 1);
    }
    __syncthreads();

    // Prologue: kick off LOOK tile loads into bufs 0..LOOK-1.
    if (tid == 0) {
#pragma unroll
        for (int k = 0; k < LOOK; k++) {
            const uint32_t bar = sbase + 8 * k;
            mbar_expect(bar, TILE_BYTES);
            bulk_g2s(sbase + SMEM_DATA + k * TILE_BYTES,
                     px + (size_t)(t_first + k) * TILE_ELEMS, TILE_BYTES, bar);
        }
    }

    int buf = 0, phase = 0;               // buf = i % NBUF, phase = (i/NBUF)&1
    for (int i = 0; i < ntiles; i++) {
        const uint32_t bar   = sbase + 8 * buf;
        const uint32_t bufsa = sbase + SMEM_DATA + buf * TILE_BYTES;
        mbar_wait(bar, phase);

        // Hoisted reload: issue the i+LOOK load NOW so it overlaps compute.
        // Buffer (i+LOOK)%NBUF was consumed at tile i-2 (all threads are past
        // barrier(i-1)); wait_group.read 1 leaves only store(i-1) pending, so
        // store(i-2)'s SMEM reads have drained (FIFO bulk group).
        if (tid == 0) {
            const int j = i + LOOK;
            if (j < ntiles) {
                bulk_store_wait_read1();
                int jb = buf + LOOK; if (jb >= NBUF) jb -= NBUF;
                const uint32_t jbar = sbase + 8 * jb;
                mbar_expect(jbar, TILE_BYTES);
                bulk_g2s(sbase + SMEM_DATA + jb * TILE_BYTES,
                         px + (size_t)(t_first + j) * TILE_ELEMS, TILE_BYTES, jbar);
            }
        }

        const bool emit = (i >= warm);    // uniform across CTA
        if (f < MN_F) {
            float* row = (float*)(smem + SMEM_DATA + buf * TILE_BYTES) + f;
            if (emit) {
#pragma unroll
                for (int t = 0; t < TT; t++) {
                    const float xv = row[t * MN_F];
                    const float e  = xv - mu;         // x_t - mu_{t-1}
                    mu = fmaf(0.01f, e, mu);
                    const float d  = 0.99f * e;       // x_t - mu_t
                    var = fmaf(0.99f, var, 0.01f * (d * d));
                    row[t * MN_F] = d * rsqrtf(var);  // in-place write-back
                }
            } else {
#pragma unroll
                for (int t = 0; t < TT; t++) {
                    const float xv = row[t * MN_F];
                    const float e  = xv - mu;
                    mu = fmaf(0.01f, e, mu);
                    const float d  = 0.99f * e;
                    var = fmaf(0.99f, var, 0.01f * (d * d));
                }
            }
        }

        // All columns written (skew bounded to <1 tile) before the S2G and
        // before the next tile's hoisted reload can touch older buffers.
        __syncthreads();

        if (tid == 0 && emit) {
            fence_proxy_async_s();
            bulk_s2g_commit(pout + (size_t)(t_first + i) * TILE_ELEMS,
                            bufsa, TILE_BYTES);
        }

        if (++buf == NBUF) { buf = 0; phase ^= 1; }
    }
    if (tid == 0) bulk_store_wait0();
}

extern "C" void kernel_launch(void* const* d_in, const int* in_sizes, int n_in,
                              void* d_out, int out_size)
{
    const float* x   = (const float*)d_in[0];
    const float* mu0 = (const float*)d_in[1];
    if (n_in >= 2 && in_sizes[0] < in_sizes[1]) {
        x   = (const float*)d_in[1];
        mu0 = (const float*)d_in[0];
    }
    float* out = (float*)d_out;

    cudaFuncSetAttribute(magnorm_kernel,
                         cudaFuncAttributeMaxDynamicSharedMemorySize, SMEM_TOTAL);
    magnorm_kernel<<<MN_B * NSPLIT, 512, SMEM_TOTAL>>>(x, mu0, out);
}